// round 17
// baseline (speedup 1.0000x reference)
#include <cuda_runtime.h>
#include <math.h>

#define BB 16
#define CC 3
#define HH 512
#define WW 512
#define HWv (HH*WW)

#define XTILES 18            // 30-wide output tiles cover 512 (last partial)
#define YB 8                 // bands of 64 rows
#define BAND 64
#define WPB 4                // warps per block
#define NT (WPB*32)          // 128
#define WARPS (XTILES*YB*BB) // 2304
#define NBLK (WARPS/WPB)     // 576
#define BLK_PER_BATCH (NBLK/BB) // 36

#define IRBLK 128
#define NIRB (BB*IRBLK)      // 2048

__device__ double   g_ir_part[NIRB];
__device__ float    g_part[NBLK];
__device__ unsigned g_done = 0;

__device__ __forceinline__ float fsqrt_fast(float x) {
    float y;
    asm("sqrt.approx.f32 %0, %1;" : "=f"(y) : "f"(x));
    return y;
}
__device__ __forceinline__ float clip01(float x) {
    return fminf(fmaxf(x, 0.f), 1.f);
}

// ---------------------------------------------------------------------------
// 1) per-batch gray sum of input_ir. gray = 0.2989 R + 0.587 G + 0.114 B
// ---------------------------------------------------------------------------
__global__ __launch_bounds__(256)
void ir_mean_kernel(const float4* __restrict__ ir) {
    int b   = blockIdx.x / IRBLK;
    int blk = blockIdx.x % IRBLK;
    const int q4  = HWv / 4;
    const int per = q4 / IRBLK;       // 512 float4 per block

    size_t base = (size_t)b * CC * q4 + (size_t)blk * per;
    const float4* r  = ir + base;
    const float4* g  = r + q4;
    const float4* bl = g + q4;

    float s = 0.f;
    #pragma unroll 2
    for (int i = threadIdx.x; i < per; i += 256) {
        float4 a = r[i], c = g[i], d = bl[i];
        s += 0.2989f * (a.x + a.y + a.z + a.w)
           + 0.587f  * (c.x + c.y + c.z + c.w)
           + 0.114f  * (d.x + d.y + d.z + d.w);
    }
    #pragma unroll
    for (int o = 16; o; o >>= 1) s += __shfl_down_sync(0xffffffffu, s, o);

    __shared__ float ws[8];
    int wid = threadIdx.x >> 5, lid = threadIdx.x & 31;
    if (lid == 0) ws[wid] = s;
    __syncthreads();
    if (wid == 0) {
        s = (lid < 8) ? ws[lid] : 0.f;
        #pragma unroll
        for (int o = 4; o; o >>= 1) s += __shfl_down_sync(0xffffffffu, s, o);
        if (lid == 0) g_ir_part[blockIdx.x] = (double)s;
    }
}

// ---------------------------------------------------------------------------
// 2) main pass: warp-autonomous streaming stencil. No smem staging, no
//    barriers in the hot loop. Lane owns one x column; horizontal Sobel
//    partials via shuffle, vertical via rolling registers.
// ---------------------------------------------------------------------------
__global__ __launch_bounds__(NT, 6)
void fusion_main_kernel(const float* __restrict__ vis,
                        const float* __restrict__ ir,
                        const float* __restrict__ outp,
                        const float* __restrict__ mask,
                        float* __restrict__ out) {
    __shared__ float  s_mean;
    __shared__ float  ws[WPB];
    __shared__ double wd[WPB];
    __shared__ bool   s_last;

    const int tid  = threadIdx.x;
    const int lane = tid & 31;
    const int w    = tid >> 5;
    const int bx   = blockIdx.x;
    const int b    = bx / BLK_PER_BATCH;            // block-uniform batch
    const int gl   = (bx % BLK_PER_BATCH) * WPB + w; // 0..143
    const int t    = gl % XTILES;
    const int yb   = gl / XTILES;                    // 0..7
    const int y0   = yb * BAND;
    const int x    = t * 30 - 1 + lane;              // loaded column

    // batch IR mean (block-uniform): one warp sums 128 partials
    if (tid < 32) {
        const double* p = g_ir_part + b * IRBLK;
        double s = p[tid] + p[tid + 32] + p[tid + 64] + p[tid + 96];
        #pragma unroll
        for (int o = 16; o; o >>= 1) s += __shfl_down_sync(0xffffffffu, s, o);
        if (tid == 0) s_mean = (float)(s * (1.0 / (double)HWv));
    }
    __syncthreads();
    const float meanb = s_mean;
    const float negm  = -0.8f * meanb;

    const bool xok   = (unsigned)x < WW;
    const bool valid = (lane >= 1) && (lane <= 30) && xok;  // output predicate
    const long long cb = (long long)b * CC * HWv + x;

    // rolling horizontal-partials: R (for gx), C (for gy); [ch*3 + field]
    float Rp[9], Rq[9], Cp[9], Cq[9];
    #pragma unroll
    for (int k = 0; k < 9; k++) { Rp[k]=Rq[k]=Cp[k]=Cq[k]=0.f; }

    float con = 0.f, gsum = 0.f, color = 0.f;

    long long ro = cb + (long long)(y0 - 1) * WW;

    #pragma unroll 3
    for (int r = 0; r < BAND + 2; r++) {           // gy = y0-1+r
        const int  gy  = y0 - 1 + r;
        const bool yok = (unsigned)gy < HH;
        const bool ok  = xok && yok;

        const bool do_pt = (r >= 1) && (r <= BAND) && valid; // pointwise row
        const bool do_st = (r >= 2) && valid;                // stencil row gy-1

        float d0v = 0.f, d2v = 0.f, dyv = 0.f;

        #pragma unroll
        for (int c = 0; c < CC; c++) {
            const long long o4 = ro + (long long)c * HWv;
            float a  = ok ? outp[o4] : 0.f;
            float m  = ok ? mask[o4] : 0.f;
            float vv = ok ? vis [o4] : 0.f;
            float qq = ok ? ir  [o4] : 0.f;

            float F = a * m;
            float V = clip01(fsqrt_fast(vv));
            float I = clip01(fmaf(1.8f, qq, negm));

            if (do_pt) {
                con += fabsf(F - fmaxf(V, I));
                float d = F - V;
                if (c == 0)      { d0v = d; dyv = 0.299f * d; }
                else if (c == 1) { dyv += 0.587f * d; }
                else             { d2v = d; dyv += 0.114f * d; }
            }

            // horizontal partials via shuffle (lanes 0/31 produce unused junk)
            float Rn0, Rn1, Rn2, Cn0, Cn1, Cn2;
            {
                float vL = __shfl_up_sync(0xffffffffu, F, 1);
                float vR = __shfl_down_sync(0xffffffffu, F, 1);
                Rn0 = vR - vL;  Cn0 = vL + 2.f * F + vR;
            }
            {
                float vL = __shfl_up_sync(0xffffffffu, V, 1);
                float vR = __shfl_down_sync(0xffffffffu, V, 1);
                Rn1 = vR - vL;  Cn1 = vL + 2.f * V + vR;
            }
            {
                float vL = __shfl_up_sync(0xffffffffu, I, 1);
                float vR = __shfl_down_sync(0xffffffffu, I, 1);
                Rn2 = vR - vL;  Cn2 = vL + 2.f * I + vR;
            }

            if (do_st) {
                float fgx = Rp[c*3+0] + 2.f * Rq[c*3+0] + Rn0;
                float vgx = Rp[c*3+1] + 2.f * Rq[c*3+1] + Rn1;
                float igx = Rp[c*3+2] + 2.f * Rq[c*3+2] + Rn2;
                float fgy = Cp[c*3+0] - Cn0;
                float vgy = Cp[c*3+1] - Cn1;
                float igy = Cp[c*3+2] - Cn2;
                gsum += fabsf(fgx - fmaxf(vgx, igx))
                      + fabsf(fgy - fmaxf(vgy, igy));
            }

            Rp[c*3+0] = Rq[c*3+0];  Rq[c*3+0] = Rn0;
            Rp[c*3+1] = Rq[c*3+1];  Rq[c*3+1] = Rn1;
            Rp[c*3+2] = Rq[c*3+2];  Rq[c*3+2] = Rn2;
            Cp[c*3+0] = Cq[c*3+0];  Cq[c*3+0] = Cn0;
            Cp[c*3+1] = Cq[c*3+1];  Cq[c*3+1] = Cn1;
            Cp[c*3+2] = Cq[c*3+2];  Cq[c*3+2] = Cn2;
        }

        if (do_pt)
            color += 0.564f * fabsf(d2v - dyv) + 0.713f * fabsf(d0v - dyv);

        ro += WW;
    }

    const float inv3 = 1.0f / (float)(BB * CC * HWv);
    const float inv1 = 1.0f / (float)(BB * HWv);
    float acc = inv3 * (0.5f * con + 0.1f * gsum) + inv1 * color;

    // warp reduce -> block reduce -> per-block partial
    #pragma unroll
    for (int o = 16; o; o >>= 1) acc += __shfl_down_sync(0xffffffffu, acc, o);
    if (lane == 0) ws[w] = acc;
    __syncthreads();
    if (tid == 0) {
        float s = 0.f;
        #pragma unroll
        for (int i = 0; i < WPB; i++) s += ws[i];
        g_part[bx] = s;
    }

    // fused finalize: last block sums all partials in double
    __threadfence();
    if (tid == 0) s_last = (atomicAdd(&g_done, 1u) == NBLK - 1);
    __syncthreads();
    if (s_last) {
        double s = 0.0;
        for (int i = tid; i < NBLK; i += NT) s += (double)g_part[i];
        #pragma unroll
        for (int o = 16; o; o >>= 1) s += __shfl_down_sync(0xffffffffu, s, o);
        if (lane == 0) wd[w] = s;
        __syncthreads();
        if (tid == 0) {
            double r = 0.0;
            #pragma unroll
            for (int i = 0; i < WPB; i++) r += wd[i];
            out[0] = (float)r;
            g_done = 0;
        }
    }
}

extern "C" void kernel_launch(void* const* d_in, const int* in_sizes, int n_in,
                              void* d_out, int out_size) {
    const float* vis  = (const float*)d_in[0];
    const float* ir   = (const float*)d_in[1];
    const float* outp = (const float*)d_in[2];
    const float* mask = (const float*)d_in[3];
    float* out = (float*)d_out;

    ir_mean_kernel<<<NIRB, 256>>>((const float4*)ir);
    fusion_main_kernel<<<NBLK, NT>>>(vis, ir, outp, mask, out);
}